// round 1
// baseline (speedup 1.0000x reference)
#include <cuda_runtime.h>
#include <cstdint>

#define N1i 8192
#define N2i 8192
#define Ci  128
#define HCi 60
#define WCi 80
// H = 480, W = 640

// Scratch (device globals are the allowed scratch mechanism)
__device__ float g_S[(size_t)N1i * (size_t)N2i];   // 256 MB score matrix
__device__ float g_rowPos[N1i];
__device__ float g_rowNeg[N1i];

// (2*sqrt(GRID^2/2) + 0.1)^2 with GRID=8  -> (2*sqrt(32)+0.1)^2
#define THR2 130.27274215762787f

// ---------------------------------------------------------------------------
// Kernel 1: positive descriptor sampling + positive hinge per keypoint
// One warp per keypoint.
// ---------------------------------------------------------------------------
__global__ void pos_kernel(const float* __restrict__ wkp1,
                           const float* __restrict__ kp1d,
                           const float* __restrict__ desc2)
{
    int gwarp = (blockIdx.x * blockDim.x + threadIdx.x) >> 5;
    int lane  = threadIdx.x & 31;
    if (gwarp >= N1i) return;

    float ky = wkp1[gwarp * 2 + 0];
    float kx = wkp1[gwarp * 2 + 1];

    float py = fminf(fmaxf(ky / 479.0f * 59.0f, 0.0f), 59.0f);
    float px = fminf(fmaxf(kx / 639.0f * 79.0f, 0.0f), 79.0f);
    int y0 = min(max((int)floorf(py), 0), HCi - 2);
    int x0 = min(max((int)floorf(px), 0), WCi - 2);
    float wy = py - (float)y0;
    float wx = px - (float)x0;
    float w00 = (1.0f - wy) * (1.0f - wx);
    float w01 = (1.0f - wy) * wx;
    float w10 = wy * (1.0f - wx);
    float w11 = wy * wx;

    int base = y0 * WCi + x0;
    float s1 = 0.0f, s2 = 0.0f;
#pragma unroll
    for (int it = 0; it < Ci / 32; ++it) {
        int c = lane + it * 32;
        const float* dp = desc2 + (size_t)c * (HCi * WCi) + base;
        float v = dp[0] * w00 + dp[1] * w01 + dp[WCi] * w10 + dp[WCi + 1] * w11;
        s1 = fmaf(v, v, s1);
        s2 = fmaf(v, kp1d[(size_t)gwarp * Ci + c], s2);
    }
#pragma unroll
    for (int o = 16; o; o >>= 1) {
        s1 += __shfl_xor_sync(0xffffffffu, s1, o);
        s2 += __shfl_xor_sync(0xffffffffu, s2, o);
    }
    if (lane == 0) {
        float nrm  = sqrtf(s1);
        float pdot = s2 / fmaxf(nrm, 1e-12f);
        g_rowPos[gwarp] = fmaxf(1.0f - pdot, 0.0f);
    }
}

// ---------------------------------------------------------------------------
// Kernel 2: S = kp1_desc @ kp2_desc^T - 5 * neighbour_mask   (fp32 SIMT GEMM)
// 128x128 CTA tile, BK=32, 256 threads, 8x8 micro-tile.
// ---------------------------------------------------------------------------
#define BM 128
#define BN 128
#define BK 32

__global__ __launch_bounds__(256, 2)
void gemm_mask_kernel(const float* __restrict__ A,
                      const float* __restrict__ B,
                      const float* __restrict__ wkp1,
                      const float* __restrict__ kp2)
{
    __shared__ float As[BK][BM + 4];
    __shared__ float Bs[BK][BN + 4];

    int tid = threadIdx.x;
    int tx  = tid & 15;       // 0..15 -> n
    int ty  = tid >> 4;       // 0..15 -> m
    int row0 = blockIdx.y * BM;
    int col0 = blockIdx.x * BN;

    float acc[8][8];
#pragma unroll
    for (int r = 0; r < 8; ++r)
#pragma unroll
        for (int c = 0; c < 8; ++c) acc[r][c] = 0.0f;

    for (int k0 = 0; k0 < Ci; k0 += BK) {
        // load tiles (float4 along K, transpose into [k][m])
#pragma unroll
        for (int i = tid * 4; i < BM * BK; i += 256 * 4) {
            int m = i >> 5;
            int k = i & 31;
            float4 v = *reinterpret_cast<const float4*>(A + (size_t)(row0 + m) * Ci + k0 + k);
            As[k + 0][m] = v.x; As[k + 1][m] = v.y; As[k + 2][m] = v.z; As[k + 3][m] = v.w;
        }
#pragma unroll
        for (int i = tid * 4; i < BN * BK; i += 256 * 4) {
            int n = i >> 5;
            int k = i & 31;
            float4 v = *reinterpret_cast<const float4*>(B + (size_t)(col0 + n) * Ci + k0 + k);
            Bs[k + 0][n] = v.x; Bs[k + 1][n] = v.y; Bs[k + 2][n] = v.z; Bs[k + 3][n] = v.w;
        }
        __syncthreads();

#pragma unroll
        for (int k = 0; k < BK; ++k) {
            float4 a0 = *reinterpret_cast<const float4*>(&As[k][ty * 8]);
            float4 a1 = *reinterpret_cast<const float4*>(&As[k][ty * 8 + 4]);
            float4 b0 = *reinterpret_cast<const float4*>(&Bs[k][tx * 8]);
            float4 b1 = *reinterpret_cast<const float4*>(&Bs[k][tx * 8 + 4]);
            float ar[8] = {a0.x, a0.y, a0.z, a0.w, a1.x, a1.y, a1.z, a1.w};
            float br[8] = {b0.x, b0.y, b0.z, b0.w, b1.x, b1.y, b1.z, b1.w};
#pragma unroll
            for (int r = 0; r < 8; ++r)
#pragma unroll
                for (int c = 0; c < 8; ++c)
                    acc[r][c] = fmaf(ar[r], br[c], acc[r][c]);
        }
        __syncthreads();
    }

    // epilogue: neighbour mask (-5) + store
    int mrow = row0 + ty * 8;
    int ncol = col0 + tx * 8;
    float2 wr[8], pc[8];
#pragma unroll
    for (int r = 0; r < 8; ++r) wr[r] = reinterpret_cast<const float2*>(wkp1)[mrow + r];
#pragma unroll
    for (int c = 0; c < 8; ++c) pc[c] = reinterpret_cast<const float2*>(kp2)[ncol + c];

#pragma unroll
    for (int r = 0; r < 8; ++r) {
#pragma unroll
        for (int c = 0; c < 8; ++c) {
            float dy = wr[r].x - pc[c].x;
            float dx = wr[r].y - pc[c].y;
            float dd = fmaf(dy, dy, dx * dx);
            if (dd <= THR2) acc[r][c] -= 5.0f;
        }
        size_t off = (size_t)(mrow + r) * N2i + ncol;
        *reinterpret_cast<float4*>(g_S + off)     = make_float4(acc[r][0], acc[r][1], acc[r][2], acc[r][3]);
        *reinterpret_cast<float4*>(g_S + off + 4) = make_float4(acc[r][4], acc[r][5], acc[r][6], acc[r][7]);
    }
}

// ---------------------------------------------------------------------------
// Kernel 3: exact per-row sum of relu(top256(v) - 0.2) via 4-pass radix select
// One CTA (256 threads) per row; row staged in smem as order-preserving keys.
// ---------------------------------------------------------------------------
__device__ __forceinline__ float key_to_float(uint32_t k)
{
    uint32_t b = (k & 0x80000000u) ? (k & 0x7fffffffu) : ~k;
    return __uint_as_float(b);
}

__global__ void topk_kernel()
{
    __shared__ uint32_t keys[N2i];     // 32 KB
    __shared__ uint32_t hist[256];
    __shared__ uint32_t s_bin, s_cntAbove;
    __shared__ float    red[256];

    int row = blockIdx.x;
    int tid = threadIdx.x;
    const float* rowp = g_S + (size_t)row * N2i;

    for (int i = tid; i < N2i; i += 256) {
        uint32_t b = __float_as_uint(rowp[i]);
        keys[i] = (b & 0x80000000u) ? ~b : (b | 0x80000000u);
    }

    uint32_t prefix = 0;
    int target = 256;
    float partial = 0.0f;
    int shift = 24;

    __syncthreads();

    for (int pass = 0; pass < 4; ++pass, shift -= 8) {
        if (tid < 256) hist[tid] = 0;
        __syncthreads();

        int hs = shift + 8;   // bits above the current digit (32 on pass 0)
        for (int i = tid; i < N2i; i += 256) {
            uint32_t k = keys[i];
            bool match = (pass == 0) || (((uint64_t)k >> hs) == (uint64_t)prefix);
            if (match) atomicAdd(&hist[(k >> shift) & 255u], 1u);
        }
        __syncthreads();

        if (tid == 0) {
            int cum = 0;
            int b = 255;
            for (; b >= 0; --b) {
                int nc = cum + (int)hist[b];
                if (nc >= target) break;
                cum = nc;
            }
            s_bin = (uint32_t)b;
            s_cntAbove = (uint32_t)cum;
        }
        __syncthreads();

        uint32_t bsel = s_bin;
        int cntAbove  = (int)s_cntAbove;

        // accumulate relu(v - 0.2) for elements strictly above the selected bin
        for (int i = tid; i < N2i; i += 256) {
            uint32_t k = keys[i];
            bool match = (pass == 0) || (((uint64_t)k >> hs) == (uint64_t)prefix);
            if (match && (((k >> shift) & 255u) > bsel)) {
                float v = key_to_float(k);
                partial += fmaxf(v - 0.2f, 0.0f);
            }
        }
        target -= cntAbove;
        prefix = (prefix << 8) | bsel;
        __syncthreads();
    }

    if (tid == 0) {
        float t = key_to_float(prefix);
        partial += (float)target * fmaxf(t - 0.2f, 0.0f);
    }

    // deterministic block reduction
    red[tid] = partial;
    __syncthreads();
#pragma unroll
    for (int s = 128; s; s >>= 1) {
        if (tid < s) red[tid] += red[tid + s];
        __syncthreads();
    }
    if (tid == 0) g_rowNeg[row] = red[0];
}

// ---------------------------------------------------------------------------
// Kernel 4: final deterministic reduction -> scalar loss
// ---------------------------------------------------------------------------
__global__ void final_kernel(float* __restrict__ out)
{
    __shared__ double red[256];
    int tid = threadIdx.x;
    double s = 0.0;
    const double balance = 256.0 / 3.0;
    for (int i = tid; i < N1i; i += 256)
        s += (double)g_rowPos[i] * balance + (double)g_rowNeg[i];
    red[tid] = s;
    __syncthreads();
#pragma unroll
    for (int st = 128; st; st >>= 1) {
        if (tid < st) red[tid] += red[tid + st];
        __syncthreads();
    }
    if (tid == 0)
        out[0] = (float)(red[0] * (1.0 / ((double)N1i * 256.0)));
}

// ---------------------------------------------------------------------------
extern "C" void kernel_launch(void* const* d_in, const int* in_sizes, int n_in,
                              void* d_out, int out_size)
{
    (void)in_sizes; (void)n_in; (void)out_size;
    // metadata order: kp1, w_kp1, kp2, kp1_desc, kp2_desc, desc2
    const float* wkp1  = (const float*)d_in[1];
    const float* kp2   = (const float*)d_in[2];
    const float* kp1d  = (const float*)d_in[3];
    const float* kp2d  = (const float*)d_in[4];
    const float* desc2 = (const float*)d_in[5];
    float* out = (float*)d_out;

    pos_kernel<<<N1i / 8, 256>>>(wkp1, kp1d, desc2);

    dim3 grid(N2i / BN, N1i / BM);
    gemm_mask_kernel<<<grid, 256>>>(kp1d, kp2d, wkp1, kp2);

    topk_kernel<<<N1i, 256>>>();

    final_kernel<<<1, 256>>>(out);
}

// round 3
// speedup vs baseline: 1.4459x; 1.4459x over previous
#include <cuda_runtime.h>
#include <cuda_bf16.h>
#include <cstdint>

#define N1i 8192
#define N2i 8192
#define Ci  128
#define HCi 60
#define WCi 80

__device__ float g_S[(size_t)N1i * (size_t)N2i];   // 256 MB score matrix
__device__ float g_rowPos[N1i];
__device__ float g_rowNeg[N1i];

#define THR2 130.27274215762787f   // (2*sqrt(32)+0.1)^2

__device__ __forceinline__ uint32_t smem_to_u32(const void* p) {
    uint32_t a;
    asm("{ .reg .u64 t; cvta.to.shared.u64 t, %1; cvt.u32.u64 %0, t; }" : "=r"(a) : "l"(p));
    return a;
}

#define LDSM_X4(r0, r1, r2, r3, addr) \
    asm volatile("ldmatrix.sync.aligned.m8n8.x4.shared.b16 {%0,%1,%2,%3}, [%4];" \
        : "=r"(r0), "=r"(r1), "=r"(r2), "=r"(r3) : "r"(addr))

#define MMA16816(c0, c1, c2, c3, a0, a1, a2, a3, b0, b1) \
    asm volatile("mma.sync.aligned.m16n8k16.row.col.f32.bf16.bf16.f32 " \
        "{%0,%1,%2,%3}, {%4,%5,%6,%7}, {%8,%9}, {%0,%1,%2,%3};" \
        : "+f"(c0), "+f"(c1), "+f"(c2), "+f"(c3) \
        : "r"(a0), "r"(a1), "r"(a2), "r"(a3), "r"(b0), "r"(b1))

// ===========================================================================
// Kernel 1: positive descriptor sampling + positive hinge (one warp per kp)
// ===========================================================================
__global__ void pos_kernel(const float* __restrict__ wkp1,
                           const float* __restrict__ kp1d,
                           const float* __restrict__ desc2)
{
    int gwarp = (blockIdx.x * blockDim.x + threadIdx.x) >> 5;
    int lane  = threadIdx.x & 31;
    if (gwarp >= N1i) return;

    float ky = wkp1[gwarp * 2 + 0];
    float kx = wkp1[gwarp * 2 + 1];
    float py = fminf(fmaxf(ky / 479.0f * 59.0f, 0.0f), 59.0f);
    float px = fminf(fmaxf(kx / 639.0f * 79.0f, 0.0f), 79.0f);
    int y0 = min(max((int)floorf(py), 0), HCi - 2);
    int x0 = min(max((int)floorf(px), 0), WCi - 2);
    float wy = py - (float)y0, wx = px - (float)x0;
    float w00 = (1.0f - wy) * (1.0f - wx);
    float w01 = (1.0f - wy) * wx;
    float w10 = wy * (1.0f - wx);
    float w11 = wy * wx;

    int base = y0 * WCi + x0;
    float s1 = 0.0f, s2 = 0.0f;
#pragma unroll
    for (int it = 0; it < Ci / 32; ++it) {
        int c = lane + it * 32;
        const float* dp = desc2 + (size_t)c * (HCi * WCi) + base;
        float v = dp[0] * w00 + dp[1] * w01 + dp[WCi] * w10 + dp[WCi + 1] * w11;
        s1 = fmaf(v, v, s1);
        s2 = fmaf(v, kp1d[(size_t)gwarp * Ci + c], s2);
    }
#pragma unroll
    for (int o = 16; o; o >>= 1) {
        s1 += __shfl_xor_sync(0xffffffffu, s1, o);
        s2 += __shfl_xor_sync(0xffffffffu, s2, o);
    }
    if (lane == 0) {
        float pdot = s2 / fmaxf(sqrtf(s1), 1e-12f);
        g_rowPos[gwarp] = fmaxf(1.0f - pdot, 0.0f);
    }
}

// ===========================================================================
// Kernel 2: mma.sync bf16-split GEMM (+mask) -> g_S
// CTA tile 128x128, K=128 fully resident. 3 accumulating passes:
//   Ahi*Bhi + Ahi*Blo + Alo*Bhi   (error ~2^-16)
// 8 warps, warp tile 64x32 (2x4 warp grid).
// ===========================================================================
#define RS 136                      // padded row stride in bf16 elems (272 B)
#define OFF_KP2  0                  // 128 * float2 = 1024 B
#define OFF_AHI  1024
#define OFF_ALO  (OFF_AHI + 128 * RS * 2)
#define OFF_BHI  (OFF_ALO + 128 * RS * 2)
#define OFF_BLO  (OFF_BHI + 128 * RS * 2)
#define GEMM_SMEM (OFF_BLO + 128 * RS * 2)   // 140288 B

__global__ __launch_bounds__(256, 1)
void gemm_mma_kernel(const float* __restrict__ A,
                     const float* __restrict__ B,
                     const float* __restrict__ wkp1,
                     const float* __restrict__ kp2)
{
    extern __shared__ char smem[];
    uint32_t sb = smem_to_u32(smem);
    int tid = threadIdx.x;
    int w   = tid >> 5;
    int l   = tid & 31;
    int row0 = blockIdx.y * 128;
    int col0 = blockIdx.x * 128;

    // stage kp2 tile
    if (tid < 128) {
        reinterpret_cast<float2*>(smem + OFF_KP2)[tid] =
            reinterpret_cast<const float2*>(kp2)[col0 + tid];
    }

    // ---- prep: load fp32 tiles, split into bf16 hi/lo in smem ----
    uint32_t* aH = reinterpret_cast<uint32_t*>(smem + OFF_AHI);
    uint32_t* aL = reinterpret_cast<uint32_t*>(smem + OFF_ALO);
    uint32_t* bH = reinterpret_cast<uint32_t*>(smem + OFF_BHI);
    uint32_t* bL = reinterpret_cast<uint32_t*>(smem + OFF_BLO);

#pragma unroll
    for (int it = 0; it < 16; ++it) {
        int i = tid + it * 256;             // float4 index over 128x32
        int r = i >> 5, c4 = i & 31;
        float4 v = reinterpret_cast<const float4*>(A + (size_t)(row0 + r) * Ci)[c4];
        __nv_bfloat162 h01 = __float22bfloat162_rn(make_float2(v.x, v.y));
        __nv_bfloat162 h23 = __float22bfloat162_rn(make_float2(v.z, v.w));
        __nv_bfloat162 l01 = __float22bfloat162_rn(make_float2(v.x - __bfloat162float(h01.x),
                                                               v.y - __bfloat162float(h01.y)));
        __nv_bfloat162 l23 = __float22bfloat162_rn(make_float2(v.z - __bfloat162float(h23.x),
                                                               v.w - __bfloat162float(h23.y)));
        int o = r * (RS / 2) + c4 * 2;
        aH[o]     = *reinterpret_cast<uint32_t*>(&h01);
        aH[o + 1] = *reinterpret_cast<uint32_t*>(&h23);
        aL[o]     = *reinterpret_cast<uint32_t*>(&l01);
        aL[o + 1] = *reinterpret_cast<uint32_t*>(&l23);
    }
#pragma unroll
    for (int it = 0; it < 16; ++it) {
        int i = tid + it * 256;
        int r = i >> 5, c4 = i & 31;
        float4 v = reinterpret_cast<const float4*>(B + (size_t)(col0 + r) * Ci)[c4];
        __nv_bfloat162 h01 = __float22bfloat162_rn(make_float2(v.x, v.y));
        __nv_bfloat162 h23 = __float22bfloat162_rn(make_float2(v.z, v.w));
        __nv_bfloat162 l01 = __float22bfloat162_rn(make_float2(v.x - __bfloat162float(h01.x),
                                                               v.y - __bfloat162float(h01.y)));
        __nv_bfloat162 l23 = __float22bfloat162_rn(make_float2(v.z - __bfloat162float(h23.x),
                                                               v.w - __bfloat162float(h23.y)));
        int o = r * (RS / 2) + c4 * 2;
        bH[o]     = *reinterpret_cast<uint32_t*>(&h01);
        bH[o + 1] = *reinterpret_cast<uint32_t*>(&h23);
        bL[o]     = *reinterpret_cast<uint32_t*>(&l01);
        bL[o + 1] = *reinterpret_cast<uint32_t*>(&l23);
    }
    __syncthreads();

    // ---- main: 3 passes x 8 k-steps of mma ----
    int wm = w & 1, wn = w >> 1;            // warp tile: rows wm*64, cols wn*32
    int g  = l >> 3, r8 = l & 7;

    // per-lane ldmatrix byte offsets (k0 added per step)
    uint32_t aoff[4], boff[2];
#pragma unroll
    for (int mt = 0; mt < 4; ++mt) {
        int row = wm * 64 + mt * 16 + (g & 1) * 8 + r8;
        int kof = (g >> 1) * 8;
        aoff[mt] = (uint32_t)((row * RS + kof) * 2);
    }
#pragma unroll
    for (int h = 0; h < 2; ++h) {
        int n = wn * 32 + h * 16 + (g >> 1) * 8 + r8;
        int kof = (g & 1) * 8;
        boff[h] = (uint32_t)((n * RS + kof) * 2);
    }

    float c[4][4][4];
#pragma unroll
    for (int mt = 0; mt < 4; ++mt)
#pragma unroll
        for (int nt = 0; nt < 4; ++nt)
#pragma unroll
            for (int q = 0; q < 4; ++q) c[mt][nt][q] = 0.0f;

    uint32_t abase[3] = {sb + OFF_AHI, sb + OFF_AHI, sb + OFF_ALO};
    uint32_t bbase[3] = {sb + OFF_BHI, sb + OFF_BLO, sb + OFF_BHI};

#pragma unroll
    for (int p = 0; p < 3; ++p) {
        uint32_t ab = abase[p], bb = bbase[p];
#pragma unroll
        for (int ks = 0; ks < 8; ++ks) {
            uint32_t k0b = (uint32_t)(ks * 32);   // 16 elems * 2B
            uint32_t a[16], bfr[8];
#pragma unroll
            for (int mt = 0; mt < 4; ++mt)
                LDSM_X4(a[mt*4], a[mt*4+1], a[mt*4+2], a[mt*4+3], ab + aoff[mt] + k0b);
            LDSM_X4(bfr[0], bfr[1], bfr[2], bfr[3], bb + boff[0] + k0b);
            LDSM_X4(bfr[4], bfr[5], bfr[6], bfr[7], bb + boff[1] + k0b);
#pragma unroll
            for (int mt = 0; mt < 4; ++mt)
#pragma unroll
                for (int nt = 0; nt < 4; ++nt)
                    MMA16816(c[mt][nt][0], c[mt][nt][1], c[mt][nt][2], c[mt][nt][3],
                             a[mt*4], a[mt*4+1], a[mt*4+2], a[mt*4+3],
                             bfr[nt*2], bfr[nt*2+1]);
        }
    }

    // ---- epilogue: neighbour mask + store ----
    const float2* kp2s = reinterpret_cast<const float2*>(smem + OFF_KP2);
#pragma unroll
    for (int mt = 0; mt < 4; ++mt) {
        int rA = row0 + wm * 64 + mt * 16 + (l >> 2);
        float2 wpA = reinterpret_cast<const float2*>(wkp1)[rA];
        float2 wpB = reinterpret_cast<const float2*>(wkp1)[rA + 8];
#pragma unroll
        for (int nt = 0; nt < 4; ++nt) {
            int ct = wn * 32 + nt * 8 + 2 * (l & 3);       // col within tile
            float2 p0 = kp2s[ct], p1 = kp2s[ct + 1];
            float v0 = c[mt][nt][0], v1 = c[mt][nt][1];
            float v2 = c[mt][nt][2], v3 = c[mt][nt][3];
            {
                float dy = wpA.x - p0.x, dx = wpA.y - p0.y;
                if (fmaf(dy, dy, dx * dx) <= THR2) v0 -= 5.0f;
                dy = wpA.x - p1.x; dx = wpA.y - p1.y;
                if (fmaf(dy, dy, dx * dx) <= THR2) v1 -= 5.0f;
                dy = wpB.x - p0.x; dx = wpB.y - p0.y;
                if (fmaf(dy, dy, dx * dx) <= THR2) v2 -= 5.0f;
                dy = wpB.x - p1.x; dx = wpB.y - p1.y;
                if (fmaf(dy, dy, dx * dx) <= THR2) v3 -= 5.0f;
            }
            size_t gc = (size_t)col0 + ct;
            *reinterpret_cast<float2*>(g_S + (size_t)rA * N2i + gc)       = make_float2(v0, v1);
            *reinterpret_cast<float2*>(g_S + (size_t)(rA + 8) * N2i + gc) = make_float2(v2, v3);
        }
    }
}

// ===========================================================================
// Kernel 3: exact per-row sum of relu(top256(v) - 0.2) via radix select
// ===========================================================================
__device__ __forceinline__ float key_to_float(uint32_t k)
{
    uint32_t b = (k & 0x80000000u) ? (k & 0x7fffffffu) : ~k;
    return __uint_as_float(b);
}

__global__ void topk_kernel()
{
    __shared__ uint32_t keys[N2i];     // 32 KB
    __shared__ uint32_t hist[256];
    __shared__ uint32_t s_bin, s_cntAbove;
    __shared__ float    red[256];

    int row = blockIdx.x;
    int tid = threadIdx.x;
    const float4* rowp = reinterpret_cast<const float4*>(g_S + (size_t)row * N2i);

#pragma unroll
    for (int it = 0; it < 8; ++it) {
        int i = tid + it * 256;
        float4 v = rowp[i];
        uint32_t b0 = __float_as_uint(v.x), b1 = __float_as_uint(v.y);
        uint32_t b2 = __float_as_uint(v.z), b3 = __float_as_uint(v.w);
        keys[i * 4 + 0] = (b0 & 0x80000000u) ? ~b0 : (b0 | 0x80000000u);
        keys[i * 4 + 1] = (b1 & 0x80000000u) ? ~b1 : (b1 | 0x80000000u);
        keys[i * 4 + 2] = (b2 & 0x80000000u) ? ~b2 : (b2 | 0x80000000u);
        keys[i * 4 + 3] = (b3 & 0x80000000u) ? ~b3 : (b3 | 0x80000000u);
    }

    uint32_t prefix = 0;
    int target = 256;
    float partial = 0.0f;
    int shift = 24;

    __syncthreads();

    for (int pass = 0; pass < 4; ++pass, shift -= 8) {
        hist[tid] = 0;
        __syncthreads();

        int hs = shift + 8;
        for (int i = tid; i < N2i; i += 256) {
            uint32_t k = keys[i];
            bool match = (pass == 0) || (((uint64_t)k >> hs) == (uint64_t)prefix);
            if (match) atomicAdd(&hist[(k >> shift) & 255u], 1u);
        }
        __syncthreads();

        if (tid == 0) {
            int cum = 0;
            int b = 255;
            for (; b >= 0; --b) {
                int nc = cum + (int)hist[b];
                if (nc >= target) break;
                cum = nc;
            }
            s_bin = (uint32_t)b;
            s_cntAbove = (uint32_t)cum;
        }
        __syncthreads();

        uint32_t bsel = s_bin;
        int cntAbove  = (int)s_cntAbove;

        for (int i = tid; i < N2i; i += 256) {
            uint32_t k = keys[i];
            bool match = (pass == 0) || (((uint64_t)k >> hs) == (uint64_t)prefix);
            if (match && (((k >> shift) & 255u) > bsel)) {
                float v = key_to_float(k);
                partial += fmaxf(v - 0.2f, 0.0f);
            }
        }
        target -= cntAbove;
        prefix = (prefix << 8) | bsel;
        __syncthreads();
    }

    if (tid == 0) {
        float t = key_to_float(prefix);
        partial += (float)target * fmaxf(t - 0.2f, 0.0f);
    }

    red[tid] = partial;
    __syncthreads();
#pragma unroll
    for (int s = 128; s; s >>= 1) {
        if (tid < s) red[tid] += red[tid + s];
        __syncthreads();
    }
    if (tid == 0) g_rowNeg[row] = red[0];
}

// ===========================================================================
// Kernel 4: final deterministic reduction
// ===========================================================================
__global__ void final_kernel(float* __restrict__ out)
{
    __shared__ double red[1024];
    int tid = threadIdx.x;
    double s = 0.0;
    const double balance = 256.0 / 3.0;
    for (int i = tid; i < N1i; i += 1024)
        s += (double)g_rowPos[i] * balance + (double)g_rowNeg[i];
    red[tid] = s;
    __syncthreads();
#pragma unroll
    for (int st = 512; st; st >>= 1) {
        if (tid < st) red[tid] += red[tid + st];
        __syncthreads();
    }
    if (tid == 0)
        out[0] = (float)(red[0] * (1.0 / ((double)N1i * 256.0)));
}

// ===========================================================================
extern "C" void kernel_launch(void* const* d_in, const int* in_sizes, int n_in,
                              void* d_out, int out_size)
{
    (void)in_sizes; (void)n_in; (void)out_size;
    const float* wkp1  = (const float*)d_in[1];
    const float* kp2   = (const float*)d_in[2];
    const float* kp1d  = (const float*)d_in[3];
    const float* kp2d  = (const float*)d_in[4];
    const float* desc2 = (const float*)d_in[5];
    float* out = (float*)d_out;

    cudaFuncSetAttribute(gemm_mma_kernel,
                         cudaFuncAttributeMaxDynamicSharedMemorySize, GEMM_SMEM);

    pos_kernel<<<N1i / 8, 256>>>(wkp1, kp1d, desc2);

    dim3 grid(N2i / 128, N1i / 128);
    gemm_mma_kernel<<<grid, 256, GEMM_SMEM>>>(kp1d, kp2d, wkp1, kp2);

    topk_kernel<<<N1i, 256>>>();

    final_kernel<<<1, 1024>>>(out);
}

// round 4
// speedup vs baseline: 1.5840x; 1.0955x over previous
#include <cuda_runtime.h>
#include <cuda_bf16.h>
#include <cstdint>

#define N1i 8192
#define N2i 8192
#define Ci  128
#define HCi 60
#define WCi 80

__device__ float g_S[(size_t)N1i * (size_t)N2i];   // 256 MB score matrix
__device__ float g_rowPos[N1i];
__device__ float g_rowNeg[N1i];

#define THR2 130.27274215762787f   // (2*sqrt(32)+0.1)^2

__device__ __forceinline__ uint32_t smem_to_u32(const void* p) {
    uint32_t a;
    asm("{ .reg .u64 t; cvta.to.shared.u64 t, %1; cvt.u32.u64 %0, t; }" : "=r"(a) : "l"(p));
    return a;
}

#define LDSM_X4(r0, r1, r2, r3, addr) \
    asm volatile("ldmatrix.sync.aligned.m8n8.x4.shared.b16 {%0,%1,%2,%3}, [%4];" \
        : "=r"(r0), "=r"(r1), "=r"(r2), "=r"(r3) : "r"(addr))

#define MMA16816(c0, c1, c2, c3, a0, a1, a2, a3, b0, b1) \
    asm volatile("mma.sync.aligned.m16n8k16.row.col.f32.bf16.bf16.f32 " \
        "{%0,%1,%2,%3}, {%4,%5,%6,%7}, {%8,%9}, {%0,%1,%2,%3};" \
        : "+f"(c0), "+f"(c1), "+f"(c2), "+f"(c3) \
        : "r"(a0), "r"(a1), "r"(a2), "r"(a3), "r"(b0), "r"(b1))

// ===========================================================================
// Kernel 1: positive descriptor sampling + positive hinge (one warp per kp)
// ===========================================================================
__global__ void pos_kernel(const float* __restrict__ wkp1,
                           const float* __restrict__ kp1d,
                           const float* __restrict__ desc2)
{
    int gwarp = (blockIdx.x * blockDim.x + threadIdx.x) >> 5;
    int lane  = threadIdx.x & 31;
    if (gwarp >= N1i) return;

    float ky = wkp1[gwarp * 2 + 0];
    float kx = wkp1[gwarp * 2 + 1];
    float py = fminf(fmaxf(ky / 479.0f * 59.0f, 0.0f), 59.0f);
    float px = fminf(fmaxf(kx / 639.0f * 79.0f, 0.0f), 79.0f);
    int y0 = min(max((int)floorf(py), 0), HCi - 2);
    int x0 = min(max((int)floorf(px), 0), WCi - 2);
    float wy = py - (float)y0, wx = px - (float)x0;
    float w00 = (1.0f - wy) * (1.0f - wx);
    float w01 = (1.0f - wy) * wx;
    float w10 = wy * (1.0f - wx);
    float w11 = wy * wx;

    int base = y0 * WCi + x0;
    float s1 = 0.0f, s2 = 0.0f;
#pragma unroll
    for (int it = 0; it < Ci / 32; ++it) {
        int c = lane + it * 32;
        const float* dp = desc2 + (size_t)c * (HCi * WCi) + base;
        float v = dp[0] * w00 + dp[1] * w01 + dp[WCi] * w10 + dp[WCi + 1] * w11;
        s1 = fmaf(v, v, s1);
        s2 = fmaf(v, kp1d[(size_t)gwarp * Ci + c], s2);
    }
#pragma unroll
    for (int o = 16; o; o >>= 1) {
        s1 += __shfl_xor_sync(0xffffffffu, s1, o);
        s2 += __shfl_xor_sync(0xffffffffu, s2, o);
    }
    if (lane == 0) {
        float pdot = s2 / fmaxf(sqrtf(s1), 1e-12f);
        g_rowPos[gwarp] = fmaxf(1.0f - pdot, 0.0f);
    }
}

// ===========================================================================
// Kernel 2: mma.sync bf16-split GEMM (+mask) -> g_S  (unchanged from R3)
// ===========================================================================
#define RS 136
#define OFF_KP2  0
#define OFF_AHI  1024
#define OFF_ALO  (OFF_AHI + 128 * RS * 2)
#define OFF_BHI  (OFF_ALO + 128 * RS * 2)
#define OFF_BLO  (OFF_BHI + 128 * RS * 2)
#define GEMM_SMEM (OFF_BLO + 128 * RS * 2)

__global__ __launch_bounds__(256, 1)
void gemm_mma_kernel(const float* __restrict__ A,
                     const float* __restrict__ B,
                     const float* __restrict__ wkp1,
                     const float* __restrict__ kp2)
{
    extern __shared__ char smem[];
    uint32_t sb = smem_to_u32(smem);
    int tid = threadIdx.x;
    int w   = tid >> 5;
    int l   = tid & 31;
    int row0 = blockIdx.y * 128;
    int col0 = blockIdx.x * 128;

    if (tid < 128) {
        reinterpret_cast<float2*>(smem + OFF_KP2)[tid] =
            reinterpret_cast<const float2*>(kp2)[col0 + tid];
    }

    uint32_t* aH = reinterpret_cast<uint32_t*>(smem + OFF_AHI);
    uint32_t* aL = reinterpret_cast<uint32_t*>(smem + OFF_ALO);
    uint32_t* bH = reinterpret_cast<uint32_t*>(smem + OFF_BHI);
    uint32_t* bL = reinterpret_cast<uint32_t*>(smem + OFF_BLO);

#pragma unroll
    for (int it = 0; it < 16; ++it) {
        int i = tid + it * 256;
        int r = i >> 5, c4 = i & 31;
        float4 v = reinterpret_cast<const float4*>(A + (size_t)(row0 + r) * Ci)[c4];
        __nv_bfloat162 h01 = __float22bfloat162_rn(make_float2(v.x, v.y));
        __nv_bfloat162 h23 = __float22bfloat162_rn(make_float2(v.z, v.w));
        __nv_bfloat162 l01 = __float22bfloat162_rn(make_float2(v.x - __bfloat162float(h01.x),
                                                               v.y - __bfloat162float(h01.y)));
        __nv_bfloat162 l23 = __float22bfloat162_rn(make_float2(v.z - __bfloat162float(h23.x),
                                                               v.w - __bfloat162float(h23.y)));
        int o = r * (RS / 2) + c4 * 2;
        aH[o]     = *reinterpret_cast<uint32_t*>(&h01);
        aH[o + 1] = *reinterpret_cast<uint32_t*>(&h23);
        aL[o]     = *reinterpret_cast<uint32_t*>(&l01);
        aL[o + 1] = *reinterpret_cast<uint32_t*>(&l23);
    }
#pragma unroll
    for (int it = 0; it < 16; ++it) {
        int i = tid + it * 256;
        int r = i >> 5, c4 = i & 31;
        float4 v = reinterpret_cast<const float4*>(B + (size_t)(col0 + r) * Ci)[c4];
        __nv_bfloat162 h01 = __float22bfloat162_rn(make_float2(v.x, v.y));
        __nv_bfloat162 h23 = __float22bfloat162_rn(make_float2(v.z, v.w));
        __nv_bfloat162 l01 = __float22bfloat162_rn(make_float2(v.x - __bfloat162float(h01.x),
                                                               v.y - __bfloat162float(h01.y)));
        __nv_bfloat162 l23 = __float22bfloat162_rn(make_float2(v.z - __bfloat162float(h23.x),
                                                               v.w - __bfloat162float(h23.y)));
        int o = r * (RS / 2) + c4 * 2;
        bH[o]     = *reinterpret_cast<uint32_t*>(&h01);
        bH[o + 1] = *reinterpret_cast<uint32_t*>(&h23);
        bL[o]     = *reinterpret_cast<uint32_t*>(&l01);
        bL[o + 1] = *reinterpret_cast<uint32_t*>(&l23);
    }
    __syncthreads();

    int wm = w & 1, wn = w >> 1;
    int g  = l >> 3, r8 = l & 7;

    uint32_t aoff[4], boff[2];
#pragma unroll
    for (int mt = 0; mt < 4; ++mt) {
        int row = wm * 64 + mt * 16 + (g & 1) * 8 + r8;
        int kof = (g >> 1) * 8;
        aoff[mt] = (uint32_t)((row * RS + kof) * 2);
    }
#pragma unroll
    for (int h = 0; h < 2; ++h) {
        int n = wn * 32 + h * 16 + (g >> 1) * 8 + r8;
        int kof = (g & 1) * 8;
        boff[h] = (uint32_t)((n * RS + kof) * 2);
    }

    float c[4][4][4];
#pragma unroll
    for (int mt = 0; mt < 4; ++mt)
#pragma unroll
        for (int nt = 0; nt < 4; ++nt)
#pragma unroll
            for (int q = 0; q < 4; ++q) c[mt][nt][q] = 0.0f;

    uint32_t abase[3] = {sb + OFF_AHI, sb + OFF_AHI, sb + OFF_ALO};
    uint32_t bbase[3] = {sb + OFF_BHI, sb + OFF_BLO, sb + OFF_BHI};

#pragma unroll
    for (int p = 0; p < 3; ++p) {
        uint32_t ab = abase[p], bb = bbase[p];
#pragma unroll
        for (int ks = 0; ks < 8; ++ks) {
            uint32_t k0b = (uint32_t)(ks * 32);
            uint32_t a[16], bfr[8];
#pragma unroll
            for (int mt = 0; mt < 4; ++mt)
                LDSM_X4(a[mt*4], a[mt*4+1], a[mt*4+2], a[mt*4+3], ab + aoff[mt] + k0b);
            LDSM_X4(bfr[0], bfr[1], bfr[2], bfr[3], bb + boff[0] + k0b);
            LDSM_X4(bfr[4], bfr[5], bfr[6], bfr[7], bb + boff[1] + k0b);
#pragma unroll
            for (int mt = 0; mt < 4; ++mt)
#pragma unroll
                for (int nt = 0; nt < 4; ++nt)
                    MMA16816(c[mt][nt][0], c[mt][nt][1], c[mt][nt][2], c[mt][nt][3],
                             a[mt*4], a[mt*4+1], a[mt*4+2], a[mt*4+3],
                             bfr[nt*2], bfr[nt*2+1]);
        }
    }

    const float2* kp2s = reinterpret_cast<const float2*>(smem + OFF_KP2);
#pragma unroll
    for (int mt = 0; mt < 4; ++mt) {
        int rA = row0 + wm * 64 + mt * 16 + (l >> 2);
        float2 wpA = reinterpret_cast<const float2*>(wkp1)[rA];
        float2 wpB = reinterpret_cast<const float2*>(wkp1)[rA + 8];
#pragma unroll
        for (int nt = 0; nt < 4; ++nt) {
            int ct = wn * 32 + nt * 8 + 2 * (l & 3);
            float2 p0 = kp2s[ct], p1 = kp2s[ct + 1];
            float v0 = c[mt][nt][0], v1 = c[mt][nt][1];
            float v2 = c[mt][nt][2], v3 = c[mt][nt][3];
            {
                float dy = wpA.x - p0.x, dx = wpA.y - p0.y;
                if (fmaf(dy, dy, dx * dx) <= THR2) v0 -= 5.0f;
                dy = wpA.x - p1.x; dx = wpA.y - p1.y;
                if (fmaf(dy, dy, dx * dx) <= THR2) v1 -= 5.0f;
                dy = wpB.x - p0.x; dx = wpB.y - p0.y;
                if (fmaf(dy, dy, dx * dx) <= THR2) v2 -= 5.0f;
                dy = wpB.x - p1.x; dx = wpB.y - p1.y;
                if (fmaf(dy, dy, dx * dx) <= THR2) v3 -= 5.0f;
            }
            size_t gc = (size_t)col0 + ct;
            *reinterpret_cast<float2*>(g_S + (size_t)rA * N2i + gc)       = make_float2(v0, v1);
            *reinterpret_cast<float2*>(g_S + (size_t)(rA + 8) * N2i + gc) = make_float2(v2, v3);
        }
    }
}

// ===========================================================================
// Kernel 3: per-row sum of relu(top256 - 0.2), radix select w/ parallel bin
// select, warp-aggregated histogram atomics, stable compaction.
// Dynamic smem: keys[8192] | buf[4096] | hist[256]  = 50176 B
// ===========================================================================
#define TK_CAP 4096
#define TK_SMEM ((N2i + TK_CAP + 256) * 4)

__device__ __forceinline__ float key_to_float(uint32_t k)
{
    uint32_t b = (k & 0x80000000u) ? (k & 0x7fffffffu) : ~k;
    return __uint_as_float(b);
}
__device__ __forceinline__ uint32_t float_to_key(uint32_t b)
{
    return (b & 0x80000000u) ? ~b : (b | 0x80000000u);
}

// inclusive block scan over 256 threads (deterministic)
__device__ __forceinline__ int block_scan_incl(int v, int* s_w)
{
    __syncthreads();                       // protect s_w reuse
    int lane = threadIdx.x & 31, wid = threadIdx.x >> 5;
    int x = v;
#pragma unroll
    for (int o = 1; o < 32; o <<= 1) {
        int t = __shfl_up_sync(0xffffffffu, x, o);
        if (lane >= o) x += t;
    }
    if (lane == 31) s_w[wid] = x;
    __syncthreads();
    if (threadIdx.x == 0) {
        int run = 0;
#pragma unroll
        for (int i = 0; i < 8; ++i) { int t = s_w[i]; s_w[i] = run; run += t; }
    }
    __syncthreads();
    return s_w[wid] + x;
}

__global__ __launch_bounds__(256)
void topk_kernel()
{
    extern __shared__ uint32_t sdyn[];
    uint32_t* keys = sdyn;                 // 8192
    uint32_t* bufp = sdyn + N2i;           // 4096
    uint32_t* hist = sdyn + N2i + TK_CAP;  // 256
    __shared__ int   s_w[8];
    __shared__ uint32_t s_bin;
    __shared__ int   s_above;
    __shared__ float red[256];

    int row = blockIdx.x;
    int tid = threadIdx.x;
    int lane = tid & 31;

    // ---- pass-1 fused load + key transform + warp-aggregated histogram ----
    hist[tid] = 0;
    __syncthreads();
    const float4* rowp = reinterpret_cast<const float4*>(g_S + (size_t)row * N2i);
#pragma unroll
    for (int it = 0; it < 8; ++it) {
        int i = tid + it * 256;
        float4 v = rowp[i];
        uint32_t kk[4] = {float_to_key(__float_as_uint(v.x)),
                          float_to_key(__float_as_uint(v.y)),
                          float_to_key(__float_as_uint(v.z)),
                          float_to_key(__float_as_uint(v.w))};
#pragma unroll
        for (int q = 0; q < 4; ++q) {
            keys[i * 4 + q] = kk[q];
            uint32_t d = kk[q] >> 24;
            unsigned mm = __match_any_sync(0xffffffffu, d);
            int leader = __ffs((int)mm) - 1;
            if (lane == leader) atomicAdd(&hist[d], (uint32_t)__popc(mm));
        }
    }
    __syncthreads();

    uint32_t* src = keys;
    int len = N2i;
    bool usePfx = false;
    uint32_t prefix = 0;
    int target = 256;
    float partial = 0.0f;
    int shift = 24;

    for (;;) {
        // ---- parallel bin select: suffix sums over 256 bins ----
        int mybin = 255 - tid;
        int hv = (int)hist[mybin];
        int incl = block_scan_incl(hv, s_w);     // count of elems in bins >= mybin
        int excl = incl - hv;
        if (excl < target && incl >= target) { s_bin = (uint32_t)mybin; s_above = excl; }
        __syncthreads();
        uint32_t b = s_bin;
        int above  = s_above;
        int cnt_eq = (int)hist[b];

        // ---- accumulate above-bin + count equal-bin (deterministic order) ----
        int mycount = 0;
        for (int i = tid; i < len; i += 256) {
            uint32_t k = src[i];
            bool valid = !usePfx || ((k >> (shift + 8)) == prefix);
            if (valid) {
                uint32_t d = (k >> shift) & 255u;
                if (d > b) partial += fmaxf(key_to_float(k) - 0.2f, 0.0f);
                else if (d == b) ++mycount;
            }
        }
        target -= above;
        prefix = (prefix << 8) | b;
        if (shift == 0) break;

        // ---- stable compaction (or prefix-mode fallback) ----
        uint32_t* dst = (src == keys) ? bufp : keys;
        int cap = (src == keys) ? TK_CAP : N2i;
        if (cnt_eq <= cap) {
            int myoff = block_scan_incl(mycount, s_w) - mycount;
            int j = myoff;
            for (int i = tid; i < len; i += 256) {
                uint32_t k = src[i];
                bool valid = !usePfx || ((k >> (shift + 8)) == prefix);
                if (valid && ((k >> shift) & 255u) == b) dst[j++] = k;
            }
            src = dst;
            len = cnt_eq;
            usePfx = false;
        } else {
            usePfx = true;
        }
        shift -= 8;

        // ---- histogram for next pass ----
        __syncthreads();
        hist[tid] = 0;
        __syncthreads();
        for (int i0 = 0; i0 < len; i0 += 256) {
            int i = i0 + tid;
            uint32_t k = (i < len) ? src[i] : 0u;
            bool valid = (i < len) && (!usePfx || ((k >> (shift + 8)) == prefix));
            unsigned mask = __ballot_sync(0xffffffffu, valid);
            if (valid) {
                uint32_t d = (k >> shift) & 255u;
                unsigned mm = __match_any_sync(mask, d);
                int leader = __ffs((int)mm) - 1;
                if (lane == leader) atomicAdd(&hist[d], (uint32_t)__popc(mm));
            }
        }
        __syncthreads();
    }

    if (tid == 0)
        partial += (float)target * fmaxf(key_to_float(prefix) - 0.2f, 0.0f);

    red[tid] = partial;
    __syncthreads();
#pragma unroll
    for (int s = 128; s; s >>= 1) {
        if (tid < s) red[tid] += red[tid + s];
        __syncthreads();
    }
    if (tid == 0) g_rowNeg[row] = red[0];
}

// ===========================================================================
// Kernel 4: final deterministic reduction
// ===========================================================================
__global__ void final_kernel(float* __restrict__ out)
{
    __shared__ double red[1024];
    int tid = threadIdx.x;
    double s = 0.0;
    const double balance = 256.0 / 3.0;
    for (int i = tid; i < N1i; i += 1024)
        s += (double)g_rowPos[i] * balance + (double)g_rowNeg[i];
    red[tid] = s;
    __syncthreads();
#pragma unroll
    for (int st = 512; st; st >>= 1) {
        if (tid < st) red[tid] += red[tid + st];
        __syncthreads();
    }
    if (tid == 0)
        out[0] = (float)(red[0] * (1.0 / ((double)N1i * 256.0)));
}

// ===========================================================================
extern "C" void kernel_launch(void* const* d_in, const int* in_sizes, int n_in,
                              void* d_out, int out_size)
{
    (void)in_sizes; (void)n_in; (void)out_size;
    const float* wkp1  = (const float*)d_in[1];
    const float* kp2   = (const float*)d_in[2];
    const float* kp1d  = (const float*)d_in[3];
    const float* kp2d  = (const float*)d_in[4];
    const float* desc2 = (const float*)d_in[5];
    float* out = (float*)d_out;

    cudaFuncSetAttribute(gemm_mma_kernel,
                         cudaFuncAttributeMaxDynamicSharedMemorySize, GEMM_SMEM);
    cudaFuncSetAttribute(topk_kernel,
                         cudaFuncAttributeMaxDynamicSharedMemorySize, TK_SMEM);

    pos_kernel<<<N1i / 8, 256>>>(wkp1, kp1d, desc2);

    dim3 grid(N2i / 128, N1i / 128);
    gemm_mma_kernel<<<grid, 256, GEMM_SMEM>>>(kp1d, kp2d, wkp1, kp2);

    topk_kernel<<<N1i, 256, TK_SMEM>>>();

    final_kernel<<<1, 1024>>>(out);
}